// round 16
// baseline (speedup 1.0000x reference)
#include <cuda_runtime.h>
#include <cuda_bf16.h>
#include <cstdint>

// yoloLoss: pred/target (4096,14,14,30) fp32 -> scalar.
// FINAL (converged, 5x verified at 35.328 us; best ncu 33.95us / 73.2% DRAM):
// per-warp 2-stage cp.async.bulk pipelines, exact-balance schedule
// (1792 warps x 14 tiles = 25088), register-hoisted compute, dual-lane copy
// issue, deterministic last-block finalize. Pinned at the effective DRAM
// read ceiling (~5.7-5.8 TB/s) for this pattern on GB300.

#define S_GRID    14.0f
#define BATCH     4096
#define NTHR      224                       // 7 warps per CTA
#define NWARP     7
#define CELL_W    30
#define WT_F      960                       // 32 cells * 30 floats
#define WT_B      3840
#define STAGES    2
#define GRID      256                       // 256 x 7 = 1792 warps
#define NWTOT     (GRID * NWARP)            // 1792
#define NC        14                        // tiles per warp, exact
#define SMEM_DYN  (NWARP * STAGES * 2 * WT_B)   // 107520 B -> 2 CTAs/SM

__device__ float    g_partials[GRID];
__device__ unsigned g_done;                 // zero-init; reset by last block

__device__ __forceinline__ unsigned smem_u32(const void* p) {
    return (unsigned)__cvta_generic_to_shared(p);
}
__device__ __forceinline__ void mbar_init(void* mbar, unsigned count) {
    asm volatile("mbarrier.init.shared.b64 [%0], %1;"
                 :: "r"(smem_u32(mbar)), "r"(count) : "memory");
}
__device__ __forceinline__ void mbar_expect_tx(void* mbar, unsigned bytes) {
    asm volatile("mbarrier.arrive.expect_tx.shared.b64 _, [%0], %1;"
                 :: "r"(smem_u32(mbar)), "r"(bytes) : "memory");
}
__device__ __forceinline__ void bulk_g2s(void* dst_smem, const void* src_gmem,
                                         unsigned bytes, void* mbar) {
    asm volatile(
        "cp.async.bulk.shared::cluster.global.mbarrier::complete_tx::bytes "
        "[%0], [%1], %2, [%3];"
        :: "r"(smem_u32(dst_smem)), "l"(src_gmem), "r"(bytes),
           "r"(smem_u32(mbar)) : "memory");
}
__device__ __forceinline__ void mbar_wait(void* mbar, unsigned parity) {
    unsigned addr = smem_u32(mbar);
    unsigned done;
    asm volatile(
        "{\n\t.reg .pred p;\n\t"
        "mbarrier.try_wait.parity.acquire.cta.shared::cta.b64 p, [%1], %2;\n\t"
        "selp.b32 %0, 1, 0, p;\n\t}"
        : "=r"(done) : "r"(addr), "r"(parity) : "memory");
    if (!done) {
        asm volatile(
            "{\n\t.reg .pred P1;\n\t"
            "W_%=:\n\t"
            "mbarrier.try_wait.parity.acquire.cta.shared::cta.b64 P1, [%0], %1, 0x989680;\n\t"
            "@P1 bra.uni D_%=;\n\t"
            "bra.uni W_%=;\n\t"
            "D_%=:\n\t}"
            :: "r"(addr), "r"(parity) : "memory");
    }
}

__device__ __forceinline__ float iou_one(
    float px, float py, float pw, float ph,
    float tx, float ty, float tw, float th)
{
    const float invS = 1.0f / S_GRID;
    float px1 = px * invS - 0.5f * pw, px2 = px * invS + 0.5f * pw;
    float py1 = py * invS - 0.5f * ph, py2 = py * invS + 0.5f * ph;
    float tx1 = tx * invS - 0.5f * tw, tx2 = tx * invS + 0.5f * tw;
    float ty1 = ty * invS - 0.5f * th, ty2 = ty * invS + 0.5f * th;
    float iw = fmaxf(fminf(px2, tx2) - fmaxf(px1, tx1), 0.0f);
    float ih = fmaxf(fminf(py2, ty2) - fmaxf(py1, ty1), 0.0f);
    float inter = iw * ih;
    float a1 = (px2 - px1) * (py2 - py1);
    float a2 = (tx2 - tx1) * (ty2 - ty1);
    return inter / (a1 + a2 - inter);
}

__global__ __launch_bounds__(NTHR, 2)
void yolo_loss_kernel(const float* __restrict__ pred,
                      const float* __restrict__ targ,
                      float* __restrict__ out)
{
    extern __shared__ __align__(16) float buf[];  // [NWARP][STAGES][pred|targ][WT_F]
    __shared__ __align__(8) unsigned long long mbar[NWARP * STAGES];
    __shared__ float red[NWARP];
    __shared__ int   is_last;

    const int tid  = threadIdx.x;
    const int lane = tid & 31;
    const int w    = tid >> 5;
    const int bid  = blockIdx.x;
    const int gw   = bid * NWARP + w;       // global warp id: 0..1791

    if (tid < NWARP * STAGES) mbar_init(&mbar[tid], 1);
    __syncthreads();

    float* wbuf = buf + (size_t)w * (STAGES * 2 * WT_F);
    unsigned long long* wmb = &mbar[w * STAGES];

    // per-lane copy source/dest select: lane 0 -> pred, lane 1 -> targ
    const float* mysrc = (lane == 0) ? pred : targ;
    const int    myoff = (lane == 0) ? 0 : 1;

    if (lane < 2) {
#pragma unroll
        for (int k = 0; k < STAGES; k++) {
            const size_t goff = (size_t)(gw + k * NWTOT) * WT_F;
            float* dst = wbuf + (size_t)(k * 2 + myoff) * WT_F;
            if (lane == 0) mbar_expect_tx(&wmb[k], 2 * WT_B);
            __syncwarp(0x3u);
            bulk_g2s(dst, mysrc + goff, WT_B, &wmb[k]);
        }
    }

    float acc = 0.0f;

    for (int c = 0; c < NC; c++) {
        const int s = c & 1;
        const unsigned parity = (unsigned)((c >> 1) & 1);
        mbar_wait(&wmb[s], parity);

        const float2* cp2 = reinterpret_cast<const float2*>(
            wbuf + (size_t)(s * 2 + 0) * WT_F + lane * CELL_W);
        const float2* ct2 = reinterpret_cast<const float2*>(
            wbuf + (size_t)(s * 2 + 1) * WT_F + lane * CELL_W);

        // hoist all SMEM reads into registers, then re-issue immediately
        float2 a[15], b[15];
#pragma unroll
        for (int k = 0; k < 15; k++) a[k] = cp2[k];
#pragma unroll
        for (int k = 0; k < 15; k++) b[k] = ct2[k];

        __syncwarp();
        if (lane < 2 && c + STAGES < NC) {
            const size_t goff = (size_t)(gw + (c + STAGES) * NWTOT) * WT_F;
            float* dst = wbuf + (size_t)(s * 2 + myoff) * WT_F;
            if (lane == 0) mbar_expect_tx(&wmb[s], 2 * WT_B);
            __syncwarp(0x3u);
            bulk_g2s(dst, mysrc + goff, WT_B, &wmb[s]);
        }

        // ---- arithmetic (registers only) ----
        float px = a[0].x, py = a[0].y, pw = a[1].x, ph_ = a[1].y, pc0 = a[2].x;
        float qx = a[2].y, qy = a[3].x, qw = a[3].y, qh  = a[4].x, pc1 = a[4].y;
        float tx = b[0].x, ty = b[0].y, tw = b[1].x, th  = b[1].y, tc0 = b[2].x;
        float ux = b[2].y, uy = b[3].x, uw = b[3].y, uh  = b[4].x, tc1 = b[4].y;

        float m  = (tc0 > 0.0f) ? 1.0f : 0.0f;
        float nm = 1.0f - m;

        float iou0 = iou_one(px, py, pw, ph_, tx, ty, tw, th);
        float iou1 = iou_one(qx, qy, qw, qh,  tx, ty, tw, th);
        bool  sec  = (iou1 > iou0);            // argmax, tie -> box 0
        float max_iou = fmaxf(iou0, iou1);

        float rx = sec ? qx : px, ry = sec ? qy : py;
        float rw = sec ? qw : pw, rh = sec ? qh : ph_;
        float rc = sec ? pc1 : pc0;
        float sx = sec ? ux : tx, sy = sec ? uy : ty;
        float sw = sec ? uw : tw, sh = sec ? uh : th;

        float dx = rx - sx, dy = ry - sy;
        float loss_xy = dx * dx + dy * dy;
        float dw = sqrtf(rw) - sqrtf(sw);
        float dh = sqrtf(rh) - sqrtf(sh);
        float loss_wh = dw * dw + dh * dh;
        float dob = rc - max_iou;
        float loss_obj = dob * dob;

        float loss_class = 0.0f;
#pragma unroll
        for (int k = 5; k < 15; k++) {         // channels 10..29
            float d0c = a[k].x - b[k].x;
            float d1c = a[k].y - b[k].y;
            loss_class = fmaf(d0c, d0c, loss_class);
            loss_class = fmaf(d1c, d1c, loss_class);
        }

        float d0 = pc0 - tc0, d1 = pc1 - tc1;
        float loss_noobj = d0 * d0 + d1 * d1;

        acc += m * (5.0f * (loss_xy + loss_wh) + loss_obj + loss_class)
             + nm * (0.5f * loss_noobj);
    }

    // ---- block reduce ----
#pragma unroll
    for (int o = 16; o > 0; o >>= 1)
        acc += __shfl_down_sync(0xFFFFFFFFu, acc, o);
    if (lane == 0) red[w] = acc;
    __syncthreads();
    if (w == 0) {
        float v = (lane < NWARP) ? red[lane] : 0.0f;
#pragma unroll
        for (int o = 4; o > 0; o >>= 1)
            v += __shfl_down_sync(0xFFFFFFFFu, v, o);
        if (lane == 0) g_partials[bid] = v;
    }

    // ---- deterministic last-block finalize ----
    if (tid == 0) {
        __threadfence();
        unsigned prev = atomicAdd(&g_done, 1u);
        is_last = (prev == (unsigned)(gridDim.x - 1));
    }
    __syncthreads();
    if (is_last) {
        __threadfence();
        float aa = 0.0f;
        for (int i = tid; i < GRID; i += NTHR)
            aa += g_partials[i];
#pragma unroll
        for (int o = 16; o > 0; o >>= 1)
            aa += __shfl_down_sync(0xFFFFFFFFu, aa, o);
        if (lane == 0) red[w] = aa;
        __syncthreads();
        if (w == 0) {
            float v = (lane < NWARP) ? red[lane] : 0.0f;
#pragma unroll
            for (int o = 4; o > 0; o >>= 1)
                v += __shfl_down_sync(0xFFFFFFFFu, v, o);
            if (lane == 0) {
                out[0] = v * (1.0f / (float)BATCH);
                g_done = 0;           // reset for next graph replay
            }
        }
    }
}

extern "C" void kernel_launch(void* const* d_in, const int* in_sizes, int n_in,
                              void* d_out, int out_size)
{
    const float* pred = (const float*)d_in[0];
    const float* targ = (const float*)d_in[1];
    float* out = (float*)d_out;

    cudaFuncSetAttribute(yolo_loss_kernel,
                         cudaFuncAttributeMaxDynamicSharedMemorySize, SMEM_DYN);
    yolo_loss_kernel<<<GRID, NTHR, SMEM_DYN>>>(pred, targ, out);
}

// round 17
// speedup vs baseline: 1.0462x; 1.0462x over previous
#include <cuda_runtime.h>
#include <cuda_bf16.h>
#include <cstdint>

// yoloLoss: pred/target (4096,14,14,30) fp32 -> scalar.
// FINAL (converged; 6 runs: bench 35.3-36.9us, ncu 34.0-35.7us, DRAM 69.6-73.2%):
// per-warp 2-stage cp.async.bulk pipelines, exact-balance schedule
// (1792 warps x 14 tiles = 25088), register-hoisted compute, dual-lane copy
// issue, deterministic last-block finalize. Pinned at the effective DRAM
// read ceiling (~5.7-5.8 TB/s) for this pattern on GB300.

#define S_GRID    14.0f
#define BATCH     4096
#define NTHR      224                       // 7 warps per CTA
#define NWARP     7
#define CELL_W    30
#define WT_F      960                       // 32 cells * 30 floats
#define WT_B      3840
#define STAGES    2
#define GRID      256                       // 256 x 7 = 1792 warps
#define NWTOT     (GRID * NWARP)            // 1792
#define NC        14                        // tiles per warp, exact
#define SMEM_DYN  (NWARP * STAGES * 2 * WT_B)   // 107520 B -> 2 CTAs/SM

__device__ float    g_partials[GRID];
__device__ unsigned g_done;                 // zero-init; reset by last block

__device__ __forceinline__ unsigned smem_u32(const void* p) {
    return (unsigned)__cvta_generic_to_shared(p);
}
__device__ __forceinline__ void mbar_init(void* mbar, unsigned count) {
    asm volatile("mbarrier.init.shared.b64 [%0], %1;"
                 :: "r"(smem_u32(mbar)), "r"(count) : "memory");
}
__device__ __forceinline__ void mbar_expect_tx(void* mbar, unsigned bytes) {
    asm volatile("mbarrier.arrive.expect_tx.shared.b64 _, [%0], %1;"
                 :: "r"(smem_u32(mbar)), "r"(bytes) : "memory");
}
__device__ __forceinline__ void bulk_g2s(void* dst_smem, const void* src_gmem,
                                         unsigned bytes, void* mbar) {
    asm volatile(
        "cp.async.bulk.shared::cluster.global.mbarrier::complete_tx::bytes "
        "[%0], [%1], %2, [%3];"
        :: "r"(smem_u32(dst_smem)), "l"(src_gmem), "r"(bytes),
           "r"(smem_u32(mbar)) : "memory");
}
__device__ __forceinline__ void mbar_wait(void* mbar, unsigned parity) {
    unsigned addr = smem_u32(mbar);
    unsigned done;
    asm volatile(
        "{\n\t.reg .pred p;\n\t"
        "mbarrier.try_wait.parity.acquire.cta.shared::cta.b64 p, [%1], %2;\n\t"
        "selp.b32 %0, 1, 0, p;\n\t}"
        : "=r"(done) : "r"(addr), "r"(parity) : "memory");
    if (!done) {
        asm volatile(
            "{\n\t.reg .pred P1;\n\t"
            "W_%=:\n\t"
            "mbarrier.try_wait.parity.acquire.cta.shared::cta.b64 P1, [%0], %1, 0x989680;\n\t"
            "@P1 bra.uni D_%=;\n\t"
            "bra.uni W_%=;\n\t"
            "D_%=:\n\t}"
            :: "r"(addr), "r"(parity) : "memory");
    }
}

__device__ __forceinline__ float iou_one(
    float px, float py, float pw, float ph,
    float tx, float ty, float tw, float th)
{
    const float invS = 1.0f / S_GRID;
    float px1 = px * invS - 0.5f * pw, px2 = px * invS + 0.5f * pw;
    float py1 = py * invS - 0.5f * ph, py2 = py * invS + 0.5f * ph;
    float tx1 = tx * invS - 0.5f * tw, tx2 = tx * invS + 0.5f * tw;
    float ty1 = ty * invS - 0.5f * th, ty2 = ty * invS + 0.5f * th;
    float iw = fmaxf(fminf(px2, tx2) - fmaxf(px1, tx1), 0.0f);
    float ih = fmaxf(fminf(py2, ty2) - fmaxf(py1, ty1), 0.0f);
    float inter = iw * ih;
    float a1 = (px2 - px1) * (py2 - py1);
    float a2 = (tx2 - tx1) * (ty2 - ty1);
    return inter / (a1 + a2 - inter);
}

__global__ __launch_bounds__(NTHR, 2)
void yolo_loss_kernel(const float* __restrict__ pred,
                      const float* __restrict__ targ,
                      float* __restrict__ out)
{
    extern __shared__ __align__(16) float buf[];  // [NWARP][STAGES][pred|targ][WT_F]
    __shared__ __align__(8) unsigned long long mbar[NWARP * STAGES];
    __shared__ float red[NWARP];
    __shared__ int   is_last;

    const int tid  = threadIdx.x;
    const int lane = tid & 31;
    const int w    = tid >> 5;
    const int bid  = blockIdx.x;
    const int gw   = bid * NWARP + w;       // global warp id: 0..1791

    if (tid < NWARP * STAGES) mbar_init(&mbar[tid], 1);
    __syncthreads();

    float* wbuf = buf + (size_t)w * (STAGES * 2 * WT_F);
    unsigned long long* wmb = &mbar[w * STAGES];

    // per-lane copy source/dest select: lane 0 -> pred, lane 1 -> targ
    const float* mysrc = (lane == 0) ? pred : targ;
    const int    myoff = (lane == 0) ? 0 : 1;

    if (lane < 2) {
#pragma unroll
        for (int k = 0; k < STAGES; k++) {
            const size_t goff = (size_t)(gw + k * NWTOT) * WT_F;
            float* dst = wbuf + (size_t)(k * 2 + myoff) * WT_F;
            if (lane == 0) mbar_expect_tx(&wmb[k], 2 * WT_B);
            __syncwarp(0x3u);
            bulk_g2s(dst, mysrc + goff, WT_B, &wmb[k]);
        }
    }

    float acc = 0.0f;

    for (int c = 0; c < NC; c++) {
        const int s = c & 1;
        const unsigned parity = (unsigned)((c >> 1) & 1);
        mbar_wait(&wmb[s], parity);

        const float2* cp2 = reinterpret_cast<const float2*>(
            wbuf + (size_t)(s * 2 + 0) * WT_F + lane * CELL_W);
        const float2* ct2 = reinterpret_cast<const float2*>(
            wbuf + (size_t)(s * 2 + 1) * WT_F + lane * CELL_W);

        // hoist all SMEM reads into registers, then re-issue immediately
        float2 a[15], b[15];
#pragma unroll
        for (int k = 0; k < 15; k++) a[k] = cp2[k];
#pragma unroll
        for (int k = 0; k < 15; k++) b[k] = ct2[k];

        __syncwarp();
        if (lane < 2 && c + STAGES < NC) {
            const size_t goff = (size_t)(gw + (c + STAGES) * NWTOT) * WT_F;
            float* dst = wbuf + (size_t)(s * 2 + myoff) * WT_F;
            if (lane == 0) mbar_expect_tx(&wmb[s], 2 * WT_B);
            __syncwarp(0x3u);
            bulk_g2s(dst, mysrc + goff, WT_B, &wmb[s]);
        }

        // ---- arithmetic (registers only) ----
        float px = a[0].x, py = a[0].y, pw = a[1].x, ph_ = a[1].y, pc0 = a[2].x;
        float qx = a[2].y, qy = a[3].x, qw = a[3].y, qh  = a[4].x, pc1 = a[4].y;
        float tx = b[0].x, ty = b[0].y, tw = b[1].x, th  = b[1].y, tc0 = b[2].x;
        float ux = b[2].y, uy = b[3].x, uw = b[3].y, uh  = b[4].x, tc1 = b[4].y;

        float m  = (tc0 > 0.0f) ? 1.0f : 0.0f;
        float nm = 1.0f - m;

        float iou0 = iou_one(px, py, pw, ph_, tx, ty, tw, th);
        float iou1 = iou_one(qx, qy, qw, qh,  tx, ty, tw, th);
        bool  sec  = (iou1 > iou0);            // argmax, tie -> box 0
        float max_iou = fmaxf(iou0, iou1);

        float rx = sec ? qx : px, ry = sec ? qy : py;
        float rw = sec ? qw : pw, rh = sec ? qh : ph_;
        float rc = sec ? pc1 : pc0;
        float sx = sec ? ux : tx, sy = sec ? uy : ty;
        float sw = sec ? uw : tw, sh = sec ? uh : th;

        float dx = rx - sx, dy = ry - sy;
        float loss_xy = dx * dx + dy * dy;
        float dw = sqrtf(rw) - sqrtf(sw);
        float dh = sqrtf(rh) - sqrtf(sh);
        float loss_wh = dw * dw + dh * dh;
        float dob = rc - max_iou;
        float loss_obj = dob * dob;

        float loss_class = 0.0f;
#pragma unroll
        for (int k = 5; k < 15; k++) {         // channels 10..29
            float d0c = a[k].x - b[k].x;
            float d1c = a[k].y - b[k].y;
            loss_class = fmaf(d0c, d0c, loss_class);
            loss_class = fmaf(d1c, d1c, loss_class);
        }

        float d0 = pc0 - tc0, d1 = pc1 - tc1;
        float loss_noobj = d0 * d0 + d1 * d1;

        acc += m * (5.0f * (loss_xy + loss_wh) + loss_obj + loss_class)
             + nm * (0.5f * loss_noobj);
    }

    // ---- block reduce ----
#pragma unroll
    for (int o = 16; o > 0; o >>= 1)
        acc += __shfl_down_sync(0xFFFFFFFFu, acc, o);
    if (lane == 0) red[w] = acc;
    __syncthreads();
    if (w == 0) {
        float v = (lane < NWARP) ? red[lane] : 0.0f;
#pragma unroll
        for (int o = 4; o > 0; o >>= 1)
            v += __shfl_down_sync(0xFFFFFFFFu, v, o);
        if (lane == 0) g_partials[bid] = v;
    }

    // ---- deterministic last-block finalize ----
    if (tid == 0) {
        __threadfence();
        unsigned prev = atomicAdd(&g_done, 1u);
        is_last = (prev == (unsigned)(gridDim.x - 1));
    }
    __syncthreads();
    if (is_last) {
        __threadfence();
        float aa = 0.0f;
        for (int i = tid; i < GRID; i += NTHR)
            aa += g_partials[i];
#pragma unroll
        for (int o = 16; o > 0; o >>= 1)
            aa += __shfl_down_sync(0xFFFFFFFFu, aa, o);
        if (lane == 0) red[w] = aa;
        __syncthreads();
        if (w == 0) {
            float v = (lane < NWARP) ? red[lane] : 0.0f;
#pragma unroll
            for (int o = 4; o > 0; o >>= 1)
                v += __shfl_down_sync(0xFFFFFFFFu, v, o);
            if (lane == 0) {
                out[0] = v * (1.0f / (float)BATCH);
                g_done = 0;           // reset for next graph replay
            }
        }
    }
}

extern "C" void kernel_launch(void* const* d_in, const int* in_sizes, int n_in,
                              void* d_out, int out_size)
{
    const float* pred = (const float*)d_in[0];
    const float* targ = (const float*)d_in[1];
    float* out = (float*)d_out;

    cudaFuncSetAttribute(yolo_loss_kernel,
                         cudaFuncAttributeMaxDynamicSharedMemorySize, SMEM_DYN);
    yolo_loss_kernel<<<GRID, NTHR, SMEM_DYN>>>(pred, targ, out);
}